// round 11
// baseline (speedup 1.0000x reference)
#include <cuda_runtime.h>
#include <cuda_bf16.h>
#include <mma.h>
#include <cstdint>

using namespace nvcuda;

#define T_ROWS    8192
#define K_DIM     4096
#define N_NODES   63
#define DEPTH_    6
#define N_LEAVES  64
#define NB_CLS    10

#define MT        64                   // rows per CTA
#define KC        64                   // k elems per chunk
#define KSPLIT    2
#define KSLICE    (K_DIM / KSPLIT)     // 2048
#define NCHUNK    (KSLICE / KC)        // 32
#define NSTAGE    4
#define NT        256                  // 4 consumer + 4 producer warps
#define NRB       (T_ROWS / MT)        // 128 row-blocks
#define NBLOCKS   (NRB * KSPLIT)       // 256 CTAs -> 2 per SM

#define LDH       72                   // bf16 leading dim -> 144 B rows
#define XTILE_B   (MT * LDH * 2)       // 9216 B
#define WTILE_B   (64 * LDH * 2)       // 9216 B
#define STAGE_B   (XTILE_B + WTILE_B)  // 18432 B
#define DYN_B     (NSTAGE * STAGE_B)   // 73728 B  (x2 CTAs = 147KB/SM, fits 228KB)
#define LDF       72

__device__ float g_z[KSPLIT * NRB * MT * 64];   // 4 MB split-K partials
__device__ int   g_rb_ticket[NRB];
__device__ float g_partial[NRB];
__device__ int   g_ticket;

static __device__ __forceinline__ uint32_t smem_u32(const void* p) {
    uint32_t a;
    asm("{ .reg .u64 t; cvta.to.shared.u64 t, %1; cvt.u32.u64 %0, t; }" : "=r"(a) : "l"(p));
    return a;
}
static __device__ __forceinline__ void mbar_init(uint32_t a, uint32_t cnt) {
    asm volatile("mbarrier.init.shared.b64 [%0], %1;" :: "r"(a), "r"(cnt) : "memory");
}
static __device__ __forceinline__ void mbar_arrive(uint32_t a) {
    asm volatile("mbarrier.arrive.shared.b64 _, [%0];" :: "r"(a) : "memory");
}
static __device__ __forceinline__ void wait_parity(uint32_t mbar, uint32_t phase) {
    uint32_t done;
    asm volatile(
        "{\n\t.reg .pred p;\n\t"
        "mbarrier.try_wait.parity.acquire.cta.shared::cta.b64 p, [%1], %2;\n\t"
        "selp.b32 %0, 1, 0, p;\n\t}"
        : "=r"(done) : "r"(mbar), "r"(phase) : "memory");
    if (!done) {
        asm volatile(
            "{\n\t.reg .pred P1;\n\t"
            "W0_%=:\n\t"
            "mbarrier.try_wait.parity.acquire.cta.shared::cta.b64 P1, [%0], %1, 0x989680;\n\t"
            "@P1 bra.uni W1_%=;\n\t"
            "bra.uni W0_%=;\n\t"
            "W1_%=:\n\t}"
            :: "r"(mbar), "r"(phase) : "memory");
    }
}
static __device__ __forceinline__ void sts128(uint32_t a, uint4 v) {
    asm volatile("st.shared.v4.b32 [%0], {%1,%2,%3,%4};"
                 :: "r"(a), "r"(v.x), "r"(v.y), "r"(v.z), "r"(v.w) : "memory");
}
static __device__ __forceinline__ uint4 pack8(float4 a, float4 b) {
    uint4 u; __nv_bfloat162 h;
    h = __floats2bfloat162_rn(a.x, a.y); u.x = *reinterpret_cast<uint32_t*>(&h);
    h = __floats2bfloat162_rn(a.z, a.w); u.y = *reinterpret_cast<uint32_t*>(&h);
    h = __floats2bfloat162_rn(b.x, b.y); u.z = *reinterpret_cast<uint32_t*>(&h);
    h = __floats2bfloat162_rn(b.z, b.w); u.w = *reinterpret_cast<uint32_t*>(&h);
    return u;
}

__global__ void __launch_bounds__(NT, 2) sdt_main(
    const float* __restrict__ X, const float* __restrict__ W,
    const float* __restrict__ bias, const float* __restrict__ beta,
    const float* __restrict__ leaf_dist, const float* __restrict__ cls_r,
    float* __restrict__ out)
{
    extern __shared__ __align__(128) unsigned char dynsm[];
    __shared__ __align__(8) unsigned long long full_mb[NSTAGE], empty_mb[NSTAGE];
    __shared__ float leaf_r[N_LEAVES];
    __shared__ float bias_s[N_NODES], beta_s[N_NODES];
    __shared__ float red_s[NT / 32];
    __shared__ int   flag_s, last_s;

    const int tid  = threadIdx.x;
    const int wid  = tid >> 5;
    const int lane = tid & 31;
    const int rb   = blockIdx.x >> 1;
    const int ks   = blockIdx.x & 1;
    const long mrow0 = (long)rb * MT;
    const long koff  = (long)ks * KSLICE;
    const uint32_t dbase = smem_u32(dynsm);

    if (tid < NSTAGE) {
        mbar_init(smem_u32(&full_mb[tid]),  4);   // 4 producer warps
        mbar_init(smem_u32(&empty_mb[tid]), 4);   // 4 consumer warps
    }
    if (tid < N_NODES) { bias_s[tid] = bias[tid]; beta_s[tid] = beta[tid]; }
    if (tid < N_LEAVES) {
        const float* ldp = leaf_dist + tid * NB_CLS;
        float mx = ldp[0];
        #pragma unroll
        for (int c = 1; c < NB_CLS; c++) mx = fmaxf(mx, ldp[c]);
        float se = 0.f, sr = 0.f;
        #pragma unroll
        for (int c = 0; c < NB_CLS; c++) {
            float e = __expf(ldp[c] - mx);
            se += e; sr += e * cls_r[c];
        }
        leaf_r[tid] = sr / se;
    }
    __syncthreads();

    wmma::fragment<wmma::accumulator, 16, 16, 16, float> acc[2][2];

    if (wid >= 4) {
        // ===== PRODUCERS (warps 4-7, 128 threads) =====
        const int pt    = tid - 128;          // 0..127
        const int c8    = pt & 7;
        const int rbase = pt >> 3;            // 0..15
        const float* Xb = X + mrow0 * K_DIM + koff;
        const float* Wb = W + koff;

        float4 st[16];
        auto ldchunk = [&](int i) {
            #pragma unroll
            for (int jj = 0; jj < 4; jj++) {
                const float4* p = reinterpret_cast<const float4*>(
                    Xb + (long)(rbase + 16 * jj) * K_DIM + i * KC + c8 * 8);
                st[2 * jj] = p[0]; st[2 * jj + 1] = p[1];
            }
            #pragma unroll
            for (int jj = 0; jj < 4; jj++) {
                int r = rbase + 16 * jj;
                if (r < N_NODES) {
                    const float4* p = reinterpret_cast<const float4*>(
                        Wb + (long)r * K_DIM + i * KC + c8 * 8);
                    st[8 + 2 * jj] = p[0]; st[9 + 2 * jj] = p[1];
                } else {
                    st[8 + 2 * jj] = make_float4(0.f, 0.f, 0.f, 0.f);
                    st[9 + 2 * jj] = st[8 + 2 * jj];
                }
            }
        };
        auto stchunk = [&](int s) {
            uint32_t base = dbase + s * STAGE_B;
            #pragma unroll
            for (int jj = 0; jj < 4; jj++)
                sts128(base + (rbase + 16 * jj) * (LDH * 2) + c8 * 16,
                       pack8(st[2 * jj], st[2 * jj + 1]));
            #pragma unroll
            for (int jj = 0; jj < 4; jj++)
                sts128(base + XTILE_B + (rbase + 16 * jj) * (LDH * 2) + c8 * 16,
                       pack8(st[8 + 2 * jj], st[9 + 2 * jj]));
        };

        ldchunk(0);
        for (int i = 0; i < NCHUNK; i++) {
            const int s = i & (NSTAGE - 1);
            if (i >= NSTAGE) wait_parity(smem_u32(&empty_mb[s]), ((i >> 2) - 1) & 1);
            stchunk(s);
            __syncwarp();
            if (lane == 0) mbar_arrive(smem_u32(&full_mb[s]));
            if (i + 1 < NCHUNK) ldchunk(i + 1);
        }
    } else {
        // ===== CONSUMERS (warps 0-3): each 32x32 tile =====
        const int mb = (wid & 1) * 32;
        const int nb = (wid >> 1) * 32;
        #pragma unroll
        for (int a = 0; a < 2; a++)
            #pragma unroll
            for (int b = 0; b < 2; b++)
                wmma::fill_fragment(acc[a][b], 0.f);

        for (int i = 0; i < NCHUNK; i++) {
            const int s = i & (NSTAGE - 1);
            wait_parity(smem_u32(&full_mb[s]), (i >> 2) & 1);
            const __nv_bfloat16* Xs = reinterpret_cast<const __nv_bfloat16*>(dynsm + s * STAGE_B);
            const __nv_bfloat16* Ws = reinterpret_cast<const __nv_bfloat16*>(dynsm + s * STAGE_B + XTILE_B);
            #pragma unroll
            for (int kk = 0; kk < KC / 16; kk++) {
                wmma::fragment<wmma::matrix_a, 16, 16, 16, __nv_bfloat16, wmma::row_major> fa0, fa1;
                wmma::fragment<wmma::matrix_b, 16, 16, 16, __nv_bfloat16, wmma::col_major> fb0, fb1;
                wmma::load_matrix_sync(fa0, Xs + (mb)      * LDH + kk * 16, LDH);
                wmma::load_matrix_sync(fa1, Xs + (mb + 16) * LDH + kk * 16, LDH);
                wmma::load_matrix_sync(fb0, Ws + (nb)      * LDH + kk * 16, LDH);
                wmma::load_matrix_sync(fb1, Ws + (nb + 16) * LDH + kk * 16, LDH);
                wmma::mma_sync(acc[0][0], fa0, fb0, acc[0][0]);
                wmma::mma_sync(acc[0][1], fa0, fb1, acc[0][1]);
                wmma::mma_sync(acc[1][0], fa1, fb0, acc[1][0]);
                wmma::mma_sync(acc[1][1], fa1, fb1, acc[1][1]);
            }
            __syncwarp();
            if (lane == 0) mbar_arrive(smem_u32(&empty_mb[s]));
        }
    }

    // ===== dump accumulators (ring drained) =====
    __syncthreads();
    float* accS = reinterpret_cast<float*>(dynsm);   // 64 x LDF fp32 = 18 KB
    if (wid < 4) {
        const int mb = (wid & 1) * 32;
        const int nb = (wid >> 1) * 32;
        #pragma unroll
        for (int a = 0; a < 2; a++)
            #pragma unroll
            for (int b = 0; b < 2; b++)
                wmma::store_matrix_sync(accS + (mb + 16 * a) * LDF + nb + 16 * b,
                                        acc[a][b], LDF, wmma::mem_row_major);
    }
    __syncthreads();

    // write partial Z (coalesced)
    float* zdst = g_z + ((long)ks * NRB + rb) * (MT * 64);
    for (int idx = tid; idx < MT * 64; idx += NT) {
        int row = idx >> 6, col = idx & 63;
        zdst[idx] = accS[row * LDF + col];
    }
    __threadfence();
    if (tid == 0) {
        int t = atomicAdd(&g_rb_ticket[rb], 1);
        flag_s = (t == 1) ? 1 : 0;
        if (t == 1) g_rb_ticket[rb] = 0;          // reset for next replay
    }
    __syncthreads();

    if (flag_s) {
        // second-arriving CTA of this row-block: combine halves + tree epilogue
        __threadfence();
        const float* zoth = g_z + ((long)(ks ^ 1) * NRB + rb) * (MT * 64);
        float rowval = 0.f;
        if (tid < MT) {
            float v[N_LEAVES];
            #pragma unroll
            for (int j = 0; j < N_LEAVES; j++) v[j] = leaf_r[j];
            #pragma unroll
            for (int lvl = DEPTH_ - 1; lvl >= 0; lvl--) {
                int base = (1 << lvl) - 1;
                #pragma unroll
                for (int i = 0; i < (1 << lvl); i++) {
                    int n = base + i;
                    float z = accS[tid * LDF + n] + zoth[tid * 64 + n];
                    float a = beta_s[n] * (z + bias_s[n]);
                    float p = 1.f / (1.f + __expf(-a));
                    v[i] = p * v[2 * i] + (1.f - p) * v[2 * i + 1];
                }
            }
            rowval = v[0];
        }
        #pragma unroll
        for (int o = 16; o > 0; o >>= 1) rowval += __shfl_down_sync(0xffffffffu, rowval, o);
        if (lane == 0) red_s[wid] = rowval;
        __syncthreads();
        if (tid == 0) {
            float s = red_s[0] + red_s[1];        // rows live in warps 0-1
            g_partial[rb] = s;
            __threadfence();
            int t = atomicAdd(&g_ticket, 1);
            last_s = (t == NRB - 1) ? 1 : 0;
            if (t == NRB - 1) g_ticket = 0;       // reset for next replay
        }
        __syncthreads();

        if (last_s && wid == 0) {
            __threadfence();
            float v = g_partial[lane] + g_partial[lane + 32] +
                      g_partial[lane + 64] + g_partial[lane + 96];
            #pragma unroll
            for (int o = 16; o > 0; o >>= 1) v += __shfl_down_sync(0xffffffffu, v, o);
            if (lane == 0) out[0] = v;
        }
    }
}

extern "C" void kernel_launch(void* const* d_in, const int* in_sizes, int n_in,
                              void* d_out, int out_size) {
    const float* X         = (const float*)d_in[0];
    const float* W         = (const float*)d_in[1];
    const float* b         = (const float*)d_in[2];
    const float* beta      = (const float*)d_in[3];
    const float* leaf_dist = (const float*)d_in[4];
    const float* cls_r     = (const float*)d_in[5];

    cudaFuncSetAttribute(sdt_main, cudaFuncAttributeMaxDynamicSharedMemorySize, DYN_B);
    sdt_main<<<NBLOCKS, NT, DYN_B>>>(X, W, b, beta, leaf_dist, cls_r, (float*)d_out);
}

// round 12
// speedup vs baseline: 1.0387x; 1.0387x over previous
#include <cuda_runtime.h>
#include <cuda_bf16.h>
#include <mma.h>
#include <cstdint>

using namespace nvcuda;

#define T_ROWS    8192
#define K_DIM     4096
#define N_NODES   63
#define DEPTH_    6
#define N_LEAVES  64
#define NB_CLS    10

#define MT        128                  // rows per CTA
#define KC        128                  // k elems per chunk (256B bf16 rows)
#define KSPLIT    2
#define KSLICE    (K_DIM / KSPLIT)     // 2048
#define NCHUNK    (KSLICE / KC)        // 16
#define NSTAGE    3
#define NT        384                  // 4 consumer + 8 producer warps
#define NRB       (T_ROWS / MT)        // 64 row-blocks
#define NBLOCKS   (NRB * KSPLIT)       // 128 CTAs -> 1 wave

#define LDH       136                  // bf16 leading dim -> 272 B rows
#define XTILE_B   (MT * LDH * 2)       // 34816 B
#define WTILE_B   (64 * LDH * 2)       // 17408 B
#define STAGE_B   (XTILE_B + WTILE_B)  // 52224 B
#define DYN_B     (NSTAGE * STAGE_B)   // 156672 B
#define LDF       72

__device__ float g_z[KSPLIT * NRB * MT * 64];   // split-K partials
__device__ int   g_rb_ticket[NRB];
__device__ float g_partial[NRB];
__device__ int   g_ticket;

static __device__ __forceinline__ uint32_t smem_u32(const void* p) {
    uint32_t a;
    asm("{ .reg .u64 t; cvta.to.shared.u64 t, %1; cvt.u32.u64 %0, t; }" : "=r"(a) : "l"(p));
    return a;
}
static __device__ __forceinline__ void mbar_init(uint32_t a, uint32_t cnt) {
    asm volatile("mbarrier.init.shared.b64 [%0], %1;" :: "r"(a), "r"(cnt) : "memory");
}
static __device__ __forceinline__ void mbar_arrive(uint32_t a) {
    asm volatile("mbarrier.arrive.shared.b64 _, [%0];" :: "r"(a) : "memory");
}
static __device__ __forceinline__ void wait_parity(uint32_t mbar, uint32_t phase) {
    uint32_t done;
    asm volatile(
        "{\n\t.reg .pred p;\n\t"
        "mbarrier.try_wait.parity.acquire.cta.shared::cta.b64 p, [%1], %2;\n\t"
        "selp.b32 %0, 1, 0, p;\n\t}"
        : "=r"(done) : "r"(mbar), "r"(phase) : "memory");
    if (!done) {
        asm volatile(
            "{\n\t.reg .pred P1;\n\t"
            "W0_%=:\n\t"
            "mbarrier.try_wait.parity.acquire.cta.shared::cta.b64 P1, [%0], %1, 0x989680;\n\t"
            "@P1 bra.uni W1_%=;\n\t"
            "bra.uni W0_%=;\n\t"
            "W1_%=:\n\t}"
            :: "r"(mbar), "r"(phase) : "memory");
    }
}
static __device__ __forceinline__ void sts128(uint32_t a, uint4 v) {
    asm volatile("st.shared.v4.b32 [%0], {%1,%2,%3,%4};"
                 :: "r"(a), "r"(v.x), "r"(v.y), "r"(v.z), "r"(v.w) : "memory");
}
static __device__ __forceinline__ uint4 pack8(float4 a, float4 b) {
    uint4 u; __nv_bfloat162 h;
    h = __floats2bfloat162_rn(a.x, a.y); u.x = *reinterpret_cast<uint32_t*>(&h);
    h = __floats2bfloat162_rn(a.z, a.w); u.y = *reinterpret_cast<uint32_t*>(&h);
    h = __floats2bfloat162_rn(b.x, b.y); u.z = *reinterpret_cast<uint32_t*>(&h);
    h = __floats2bfloat162_rn(b.z, b.w); u.w = *reinterpret_cast<uint32_t*>(&h);
    return u;
}

__global__ void __launch_bounds__(NT, 1) sdt_main(
    const float* __restrict__ X, const float* __restrict__ W,
    const float* __restrict__ bias, const float* __restrict__ beta,
    const float* __restrict__ leaf_dist, const float* __restrict__ cls_r,
    float* __restrict__ out)
{
    extern __shared__ __align__(128) unsigned char dynsm[];
    __shared__ __align__(8) unsigned long long full_mb[NSTAGE], empty_mb[NSTAGE];
    __shared__ float leaf_r[N_LEAVES];
    __shared__ float bias_s[N_NODES], beta_s[N_NODES];
    __shared__ float red_s[NT / 32];
    __shared__ int   flag_s, last_s;

    const int tid  = threadIdx.x;
    const int wid  = tid >> 5;
    const int lane = tid & 31;
    const int rb   = blockIdx.x >> 1;
    const int ks   = blockIdx.x & 1;
    const long mrow0 = (long)rb * MT;
    const long koff  = (long)ks * KSLICE;
    const uint32_t dbase = smem_u32(dynsm);

    if (tid < NSTAGE) {
        mbar_init(smem_u32(&full_mb[tid]),  8);   // 8 producer warps
        mbar_init(smem_u32(&empty_mb[tid]), 4);   // 4 consumer warps
    }
    if (tid < N_NODES) { bias_s[tid] = bias[tid]; beta_s[tid] = beta[tid]; }
    if (tid < N_LEAVES) {
        const float* ldp = leaf_dist + tid * NB_CLS;
        float mx = ldp[0];
        #pragma unroll
        for (int c = 1; c < NB_CLS; c++) mx = fmaxf(mx, ldp[c]);
        float se = 0.f, sr = 0.f;
        #pragma unroll
        for (int c = 0; c < NB_CLS; c++) {
            float e = __expf(ldp[c] - mx);
            se += e; sr += e * cls_r[c];
        }
        leaf_r[tid] = sr / se;
    }
    __syncthreads();

    wmma::fragment<wmma::accumulator, 16, 16, 16, float> acc[2][4];

    if (wid >= 4) {
        // ===== PRODUCERS (warps 4-11, 256 threads) =====
        // Per chunk: 3072 16B-units (X: 2048, W: 1024) -> 12 units/thread,
        // staged as two register halves of 6 units (loads issued 1 chunk ahead).
        const int pt = tid - 128;             // 0..255
        const float* Xb = X + mrow0 * K_DIM + koff;
        const float* Wb = W + koff;

        float4 R0[12], R1[12];
        auto ldhalf = [&](float4* r, int i, int h) {
            #pragma unroll
            for (int j = 0; j < 6; j++) {
                const int jj = h * 6 + j;
                if (jj < 8) {                  // X unit
                    int u = pt + 256 * jj;
                    int row = u >> 4, c = u & 15;
                    const float4* p = reinterpret_cast<const float4*>(
                        Xb + (long)row * K_DIM + i * KC + c * 8);
                    r[2 * j] = p[0]; r[2 * j + 1] = p[1];
                } else {                       // W unit
                    int u = pt + 256 * (jj - 8);
                    int row = u >> 4, c = u & 15;
                    if (row < N_NODES) {
                        const float4* p = reinterpret_cast<const float4*>(
                            Wb + (long)row * K_DIM + i * KC + c * 8);
                        r[2 * j] = p[0]; r[2 * j + 1] = p[1];
                    } else {
                        r[2 * j] = make_float4(0.f, 0.f, 0.f, 0.f);
                        r[2 * j + 1] = r[2 * j];
                    }
                }
            }
        };
        auto sthalf = [&](float4* r, int s, int h) {
            const uint32_t base = dbase + s * STAGE_B;
            #pragma unroll
            for (int j = 0; j < 6; j++) {
                const int jj = h * 6 + j;
                uint32_t addr;
                if (jj < 8) {
                    int u = pt + 256 * jj;
                    int row = u >> 4, c = u & 15;
                    addr = base + row * (LDH * 2) + c * 16;
                } else {
                    int u = pt + 256 * (jj - 8);
                    int row = u >> 4, c = u & 15;
                    addr = base + XTILE_B + row * (LDH * 2) + c * 16;
                }
                sts128(addr, pack8(r[2 * j], r[2 * j + 1]));
            }
        };

        ldhalf(R0, 0, 0);
        ldhalf(R1, 0, 1);
        int s_p = 0, ph_e = 0;                 // fill cursor / empty-wait phase
        for (int i = 0; i < NCHUNK; i++) {
            if (i >= NSTAGE) {
                wait_parity(smem_u32(&empty_mb[s_p]), ph_e);
                if (s_p == NSTAGE - 1) {}      // phase handled below
            }
            sthalf(R0, s_p, 0);
            if (i + 1 < NCHUNK) ldhalf(R0, i + 1, 0);
            sthalf(R1, s_p, 1);
            if (i + 1 < NCHUNK) ldhalf(R1, i + 1, 1);
            __syncwarp();
            if (lane == 0) mbar_arrive(smem_u32(&full_mb[s_p]));
            // advance cursors
            if (i >= NSTAGE) {                 // empty-wait cursor advanced with s_p wrap
                if (s_p == NSTAGE - 1) ph_e ^= 1;
            }
            if (++s_p == NSTAGE) s_p = 0;
        }
    } else {
        // ===== CONSUMERS (warps 0-3): each 32 rows x 64 cols =====
        const int mb = wid * 32;
        #pragma unroll
        for (int a = 0; a < 2; a++)
            #pragma unroll
            for (int b = 0; b < 4; b++)
                wmma::fill_fragment(acc[a][b], 0.f);

        int s_c = 0, ph_c = 0;
        for (int i = 0; i < NCHUNK; i++) {
            wait_parity(smem_u32(&full_mb[s_c]), ph_c);
            const __nv_bfloat16* Xs = reinterpret_cast<const __nv_bfloat16*>(dynsm + s_c * STAGE_B);
            const __nv_bfloat16* Ws = reinterpret_cast<const __nv_bfloat16*>(dynsm + s_c * STAGE_B + XTILE_B);
            #pragma unroll
            for (int kk = 0; kk < KC / 16; kk++) {
                wmma::fragment<wmma::matrix_a, 16, 16, 16, __nv_bfloat16, wmma::row_major> fa0, fa1;
                wmma::load_matrix_sync(fa0, Xs + (mb)      * LDH + kk * 16, LDH);
                wmma::load_matrix_sync(fa1, Xs + (mb + 16) * LDH + kk * 16, LDH);
                #pragma unroll
                for (int b = 0; b < 4; b++) {
                    wmma::fragment<wmma::matrix_b, 16, 16, 16, __nv_bfloat16, wmma::col_major> fb;
                    wmma::load_matrix_sync(fb, Ws + (b * 16) * LDH + kk * 16, LDH);
                    wmma::mma_sync(acc[0][b], fa0, fb, acc[0][b]);
                    wmma::mma_sync(acc[1][b], fa1, fb, acc[1][b]);
                }
            }
            __syncwarp();
            if (lane == 0) mbar_arrive(smem_u32(&empty_mb[s_c]));
            if (++s_c == NSTAGE) { s_c = 0; ph_c ^= 1; }
        }
    }

    // ===== dump accumulators (ring drained) =====
    __syncthreads();
    float* accS = reinterpret_cast<float*>(dynsm);   // 128 x LDF fp32 = 36 KB
    if (wid < 4) {
        const int mb = wid * 32;
        #pragma unroll
        for (int a = 0; a < 2; a++)
            #pragma unroll
            for (int b = 0; b < 4; b++)
                wmma::store_matrix_sync(accS + (mb + 16 * a) * LDF + 16 * b,
                                        acc[a][b], LDF, wmma::mem_row_major);
    }
    __syncthreads();

    // write partial Z (coalesced)
    float* zdst = g_z + ((long)ks * NRB + rb) * (MT * 64);
    for (int idx = tid; idx < MT * 64; idx += NT) {
        int row = idx >> 6, col = idx & 63;
        zdst[idx] = accS[row * LDF + col];
    }
    __threadfence();
    if (tid == 0) {
        int t = atomicAdd(&g_rb_ticket[rb], 1);
        flag_s = (t == 1) ? 1 : 0;
        if (t == 1) g_rb_ticket[rb] = 0;          // reset for next replay
    }
    __syncthreads();

    if (flag_s) {
        __threadfence();
        const float* zoth = g_z + ((long)(ks ^ 1) * NRB + rb) * (MT * 64);
        float rowval = 0.f;
        if (tid < MT) {
            float v[N_LEAVES];
            #pragma unroll
            for (int j = 0; j < N_LEAVES; j++) v[j] = leaf_r[j];
            #pragma unroll
            for (int lvl = DEPTH_ - 1; lvl >= 0; lvl--) {
                int base = (1 << lvl) - 1;
                #pragma unroll
                for (int i = 0; i < (1 << lvl); i++) {
                    int n = base + i;
                    float z = accS[tid * LDF + n] + zoth[tid * 64 + n];
                    float a = beta_s[n] * (z + bias_s[n]);
                    float p = 1.f / (1.f + __expf(-a));
                    v[i] = p * v[2 * i] + (1.f - p) * v[2 * i + 1];
                }
            }
            rowval = v[0];
        }
        #pragma unroll
        for (int o = 16; o > 0; o >>= 1) rowval += __shfl_down_sync(0xffffffffu, rowval, o);
        if (lane == 0) red_s[wid] = rowval;
        __syncthreads();
        if (tid == 0) {
            float s = red_s[0] + red_s[1] + red_s[2] + red_s[3];
            g_partial[rb] = s;
            __threadfence();
            int t = atomicAdd(&g_ticket, 1);
            last_s = (t == NRB - 1) ? 1 : 0;
            if (t == NRB - 1) g_ticket = 0;
        }
        __syncthreads();

        if (last_s && wid == 0) {
            __threadfence();
            float v = g_partial[lane] + g_partial[lane + 32];
            #pragma unroll
            for (int o = 16; o > 0; o >>= 1) v += __shfl_down_sync(0xffffffffu, v, o);
            if (lane == 0) out[0] = v;
        }
    }
}

extern "C" void kernel_launch(void* const* d_in, const int* in_sizes, int n_in,
                              void* d_out, int out_size) {
    const float* X         = (const float*)d_in[0];
    const float* W         = (const float*)d_in[1];
    const float* b         = (const float*)d_in[2];
    const float* beta      = (const float*)d_in[3];
    const float* leaf_dist = (const float*)d_in[4];
    const float* cls_r     = (const float*)d_in[5];

    cudaFuncSetAttribute(sdt_main, cudaFuncAttributeMaxDynamicSharedMemorySize, DYN_B);
    sdt_main<<<NBLOCKS, NT, DYN_B>>>(X, W, b, beta, leaf_dist, cls_r, (float*)d_out);
}